// round 5
// baseline (speedup 1.0000x reference)
#include <cuda_runtime.h>
#include <math.h>

#define NN 16384
#define CC 64
#define KK 40
#define TILE 512

// ---------------- scratch (device globals; no allocation allowed) ----------------
__device__ float  g_h[NN * CC];        // propagated features h = x@w_h + b_h
__device__ float4 g_s4[NN];            // learned coords (x,y,z,|s|^2)
__device__ int    g_knn[NN * KK];      // neighbor indices
__device__ float  g_M[NN * 2 * CC];    // [mean | max] aggregation
__device__ float  g_t[NN * CC];        // xgn + x (input to BN2)
__device__ float  g_u[NN * CC];        // y + z (input to BN3)
__device__ float  g_sum2[CC], g_sumsq2[CC], g_sum3[CC], g_sumsq3[CC];
__device__ float  g_a2[CC], g_b2[CC], g_a3[CC], g_b3[CC];

// ---------------- K0: zero BN accumulators (must run every replay) ----------------
__global__ void k_zero() {
    int i = threadIdx.x;
    if (i < CC) { g_sum2[i] = 0.f; g_sumsq2[i] = 0.f; g_sum3[i] = 0.f; g_sumsq3[i] = 0.f; }
}

// ---------------- K1: h = x@w_h + b_h ; s = x@w_s ; store (s, |s|^2) ----------------
__global__ void __launch_bounds__(256) k_proj(
    const float* __restrict__ x, const float* __restrict__ w_h,
    const float* __restrict__ b_h, const float* __restrict__ w_s)
{
    __shared__ float wh[64 * 64];
    __shared__ float ws[64 * 4];
    __shared__ float bh[64];
    __shared__ float xr[4][64];
    int tid = threadIdx.x;
    for (int i = tid; i < 4096; i += 256) wh[i] = w_h[i];
    if (tid < 192) { int k = tid / 3, j = tid % 3; ws[k * 4 + j] = w_s[tid]; }
    if (tid < 64) bh[tid] = b_h[tid];
    __syncthreads();

    int c = tid & 63, sub = tid >> 6;
    int base = blockIdx.x * 128;
    for (int it = 0; it < 32; it++) {
        int n = base + it * 4 + sub;
        xr[sub][c] = x[n * 64 + c];
        __syncthreads();
        float acc = bh[c];
#pragma unroll
        for (int k = 0; k < 64; k++) acc = fmaf(xr[sub][k], wh[k * 64 + c], acc);
        g_h[n * 64 + c] = acc;
        if (c == 0) {
            float s0 = 0.f, s1 = 0.f, s2 = 0.f;
#pragma unroll
            for (int k = 0; k < 64; k++) {
                float xv = xr[sub][k];
                s0 = fmaf(xv, ws[k * 4 + 0], s0);
                s1 = fmaf(xv, ws[k * 4 + 1], s1);
                s2 = fmaf(xv, ws[k * 4 + 2], s2);
            }
            g_s4[n] = make_float4(s0, s1, s2, fmaf(s0, s0, fmaf(s1, s1, s2 * s2)));
        }
        __syncthreads();
    }
}

// ---------------- K2: brute-force exact kNN (K=40, includes self) ----------------
__device__ __forceinline__ void insert40(float* sd, int* si, int tid, float d, int j) {
    int k = KK - 1;
    while (k > 0) {
        float prev = sd[(k - 1) * 256 + tid];
        if (prev <= d) break;
        sd[k * 256 + tid] = prev;
        si[k * 256 + tid] = si[(k - 1) * 256 + tid];
        k--;
    }
    sd[k * 256 + tid] = d;
    si[k * 256 + tid] = j;
}

extern __shared__ char dynraw[];

__global__ void __launch_bounds__(256) k_knn()
{
    float*  sd   = (float*)dynraw;                       // [40][256]
    int*    si   = (int*)(dynraw + KK * 256 * 4);        // [40][256]
    float4* tile = (float4*)(dynraw + 2 * KK * 256 * 4); // [TILE]

    int tid = threadIdx.x;
    int q = tid >> 2, p = tid & 3;
    int Q = blockIdx.x * 64 + q;
    float4 qs = g_s4[Q];
    float qx = qs.x, qy = qs.y, qz = qs.z;

#pragma unroll
    for (int k = 0; k < KK; k++) { sd[k * 256 + tid] = 3.4e38f; si[k * 256 + tid] = -1; }
    float worst = 3.4e38f;

    for (int c0 = 0; c0 < NN; c0 += TILE) {
        __syncthreads();
        for (int j = tid; j < TILE; j += 256) tile[j] = g_s4[c0 + j];
        __syncthreads();
        // part p handles candidates p, p+4, p+8, ... ; unrolled 4-wide
        for (int b0 = p; b0 < TILE; b0 += 16) {
            float4 cA = tile[b0];
            float4 cB = tile[b0 + 4];
            float4 cC = tile[b0 + 8];
            float4 cD = tile[b0 + 12];
            float dxA = qx - cA.x, dyA = qy - cA.y, dzA = qz - cA.z;
            float dxB = qx - cB.x, dyB = qy - cB.y, dzB = qz - cB.z;
            float dxC = qx - cC.x, dyC = qy - cC.y, dzC = qz - cC.z;
            float dxD = qx - cD.x, dyD = qy - cD.y, dzD = qz - cD.z;
            float dA = fmaf(dxA, dxA, fmaf(dyA, dyA, dzA * dzA));
            float dB = fmaf(dxB, dxB, fmaf(dyB, dyB, dzB * dzB));
            float dC = fmaf(dxC, dxC, fmaf(dyC, dyC, dzC * dzC));
            float dD = fmaf(dxD, dxD, fmaf(dyD, dyD, dzD * dzD));
            if (dA < worst) { insert40(sd, si, tid, dA, c0 + b0);      worst = sd[(KK - 1) * 256 + tid]; }
            if (dB < worst) { insert40(sd, si, tid, dB, c0 + b0 + 4);  worst = sd[(KK - 1) * 256 + tid]; }
            if (dC < worst) { insert40(sd, si, tid, dC, c0 + b0 + 8);  worst = sd[(KK - 1) * 256 + tid]; }
            if (dD < worst) { insert40(sd, si, tid, dD, c0 + b0 + 12); worst = sd[(KK - 1) * 256 + tid]; }
        }
    }
    __syncthreads();

    // merge the 4 sorted partitions of each query (thread with p==0; columns tid..tid+3)
    if (p == 0) {
        int k0 = 0, k1 = 0, k2 = 0, k3 = 0;
        for (int r = 0; r < KK; r++) {
            float d0 = (k0 < KK) ? sd[k0 * 256 + tid + 0] : 3.4e38f;
            float d1 = (k1 < KK) ? sd[k1 * 256 + tid + 1] : 3.4e38f;
            float d2 = (k2 < KK) ? sd[k2 * 256 + tid + 2] : 3.4e38f;
            float d3 = (k3 < KK) ? sd[k3 * 256 + tid + 3] : 3.4e38f;
            int sel = 0; float dm = d0;
            if (d1 < dm) { dm = d1; sel = 1; }
            if (d2 < dm) { dm = d2; sel = 2; }
            if (d3 < dm) { dm = d3; sel = 3; }
            int jw;
            if      (sel == 0) { jw = si[k0 * 256 + tid + 0]; k0++; }
            else if (sel == 1) { jw = si[k1 * 256 + tid + 1]; k1++; }
            else if (sel == 2) { jw = si[k2 * 256 + tid + 2]; k2++; }
            else               { jw = si[k3 * 256 + tid + 3]; k3++; }
            g_knn[Q * KK + r] = jw;
        }
    }
}

// ---------------- K3a: edge weights + mean/max message aggregation ----------------
__global__ void __launch_bounds__(256) k_gather()
{
    __shared__ int   jl[4][KK];
    __shared__ float wl[4][KK];
    int tid = threadIdx.x;
    int g = tid >> 6, c = tid & 63;
    int i = blockIdx.x * 4 + g;
    if (c < KK) {
        int j = g_knn[i * KK + c];
        float4 sj = g_s4[j];
        float4 si_ = g_s4[i];
        float dx = si_.x - sj.x, dy = si_.y - sj.y, dz = si_.z - sj.z;
        float d2 = dx * dx + dy * dy + dz * dz;
        jl[g][c] = j;
        wl[g][c] = expf(-(d2 + 1e-6f));
    }
    __syncthreads();
    float sum = 0.f, mx = -3.4e38f;
#pragma unroll
    for (int k = 0; k < KK; k++) {
        float m = wl[g][k] * g_h[jl[g][k] * 64 + c];
        sum += m;
        mx = fmaxf(mx, m);
    }
    g_M[i * 128 + c] = sum * (1.0f / KK);
    g_M[i * 128 + 64 + c] = mx;
}

// ---------------- K3b: t = [mean|max|x] @ w_lin + b_lin + x ; BN2 partial sums ----------------
__global__ void __launch_bounds__(256) k_lin(
    const float* __restrict__ x, const float* __restrict__ w_lin,
    const float* __restrict__ b_lin)
{
    float* wl = (float*)dynraw;              // [192*64]
    float* ar = (float*)dynraw + 192 * 64;   // [4][192]
    __shared__ float bl[64];
    __shared__ float red[2][4][64];
    int tid = threadIdx.x;
    for (int i = tid; i < 192 * 64; i += 256) wl[i] = w_lin[i];
    if (tid < 64) bl[tid] = b_lin[tid];
    __syncthreads();

    int c = tid & 63, sub = tid >> 6;
    int base = blockIdx.x * 128;
    float psum = 0.f, psq = 0.f;
    for (int it = 0; it < 32; it++) {
        int n = base + it * 4 + sub;
        ar[sub * 192 + c]       = g_M[n * 128 + c];
        ar[sub * 192 + 64 + c]  = g_M[n * 128 + 64 + c];
        ar[sub * 192 + 128 + c] = x[n * 64 + c];
        __syncthreads();
        float acc = bl[c] + ar[sub * 192 + 128 + c];   // + residual x
#pragma unroll
        for (int f = 0; f < 192; f++) acc = fmaf(ar[sub * 192 + f], wl[f * 64 + c], acc);
        g_t[n * 64 + c] = acc;
        psum += acc;
        psq = fmaf(acc, acc, psq);
        __syncthreads();
    }
    red[0][sub][c] = psum;
    red[1][sub][c] = psq;
    __syncthreads();
    if (sub == 0) {
        float s  = red[0][0][c] + red[0][1][c] + red[0][2][c] + red[0][3][c];
        float s2 = red[1][0][c] + red[1][1][c] + red[1][2][c] + red[1][3][c];
        atomicAdd(&g_sum2[c], s);
        atomicAdd(&g_sumsq2[c], s2);
    }
}

// ---------------- K4/K6: finalize BN affine params ----------------
__global__ void k_bnfin(const float* __restrict__ gamma, const float* __restrict__ beta, int which)
{
    int c = threadIdx.x;
    if (c < CC) {
        float s  = which ? g_sum3[c]   : g_sum2[c];
        float s2 = which ? g_sumsq3[c] : g_sumsq2[c];
        float mu  = s * (1.0f / NN);
        float var = s2 * (1.0f / NN) - mu * mu;
        float ai = gamma[c] * rsqrtf(var + 1e-5f);
        float bi = beta[c] - ai * mu;
        if (which) { g_a3[c] = ai; g_b3[c] = bi; }
        else       { g_a2[c] = ai; g_b2[c] = bi; }
    }
}

// ---------------- K5: y = BN2(t); z = elu(y@w_p1+b_p1)@w_p2+b_p2; u = y+z ; BN3 sums ----------------
__global__ void __launch_bounds__(256) k_mlp(
    const float* __restrict__ w_p1, const float* __restrict__ b_p1,
    const float* __restrict__ w_p2, const float* __restrict__ b_p2)
{
    __shared__ float w1[4096], w2[4096], b1s[64], b2s[64], aas[64], bbs[64];
    __shared__ float yr[4][64], vr[4][64];
    __shared__ float red[2][4][64];
    int tid = threadIdx.x;
    for (int i = tid; i < 4096; i += 256) { w1[i] = w_p1[i]; w2[i] = w_p2[i]; }
    if (tid < 64) { b1s[tid] = b_p1[tid]; b2s[tid] = b_p2[tid]; aas[tid] = g_a2[tid]; bbs[tid] = g_b2[tid]; }
    __syncthreads();

    int c = tid & 63, sub = tid >> 6;
    int base = blockIdx.x * 128;
    float psum = 0.f, psq = 0.f;
    for (int it = 0; it < 32; it++) {
        int n = base + it * 4 + sub;
        float yv = fmaf(aas[c], g_t[n * 64 + c], bbs[c]);
        yr[sub][c] = yv;
        __syncthreads();
        float a1 = b1s[c];
#pragma unroll
        for (int k = 0; k < 64; k++) a1 = fmaf(yr[sub][k], w1[k * 64 + c], a1);
        float v = a1 > 0.f ? a1 : expm1f(a1);
        vr[sub][c] = v;
        __syncthreads();
        float a2v = b2s[c];
#pragma unroll
        for (int k = 0; k < 64; k++) a2v = fmaf(vr[sub][k], w2[k * 64 + c], a2v);
        float u = yv + a2v;
        g_u[n * 64 + c] = u;
        psum += u;
        psq = fmaf(u, u, psq);
        __syncthreads();
    }
    red[0][sub][c] = psum;
    red[1][sub][c] = psq;
    __syncthreads();
    if (sub == 0) {
        float s  = red[0][0][c] + red[0][1][c] + red[0][2][c] + red[0][3][c];
        float s2 = red[1][0][c] + red[1][1][c] + red[1][2][c] + red[1][3][c];
        atomicAdd(&g_sum3[c], s);
        atomicAdd(&g_sumsq3[c], s2);
    }
}

// ---------------- K7: out = BN3(u) ----------------
__global__ void __launch_bounds__(256) k_out(float* __restrict__ out)
{
    int idx = blockIdx.x * 256 + threadIdx.x;   // over N*C/4 float4
    const float4* u4 = (const float4*)g_u;
    float4 v = u4[idx];
    int c = (idx * 4) & 63;
    float4 r;
    r.x = fmaf(g_a3[c + 0], v.x, g_b3[c + 0]);
    r.y = fmaf(g_a3[c + 1], v.y, g_b3[c + 1]);
    r.z = fmaf(g_a3[c + 2], v.z, g_b3[c + 2]);
    r.w = fmaf(g_a3[c + 3], v.w, g_b3[c + 3]);
    ((float4*)out)[idx] = r;
}

// ---------------- launch ----------------
extern "C" void kernel_launch(void* const* d_in, const int* in_sizes, int n_in,
                              void* d_out, int out_size)
{
    const float* x     = (const float*)d_in[0];
    const float* w_s   = (const float*)d_in[1];
    const float* w_h   = (const float*)d_in[2];
    const float* b_h   = (const float*)d_in[3];
    const float* w_lin = (const float*)d_in[4];
    const float* b_lin = (const float*)d_in[5];
    const float* w_p1  = (const float*)d_in[6];
    const float* b_p1  = (const float*)d_in[7];
    const float* w_p2  = (const float*)d_in[8];
    const float* b_p2  = (const float*)d_in[9];
    const float* gamma2 = (const float*)d_in[10];
    const float* beta2  = (const float*)d_in[11];
    const float* gamma3 = (const float*)d_in[12];
    const float* beta3  = (const float*)d_in[13];
    float* out = (float*)d_out;

    const int knn_smem = 2 * KK * 256 * 4 + TILE * 16;   // 90112 B
    const int lin_smem = (192 * 64 + 4 * 192) * 4;       // 52224 B
    cudaFuncSetAttribute(k_knn, cudaFuncAttributeMaxDynamicSharedMemorySize, knn_smem);
    cudaFuncSetAttribute(k_lin, cudaFuncAttributeMaxDynamicSharedMemorySize, lin_smem);

    k_zero<<<1, 64>>>();
    k_proj<<<128, 256>>>(x, w_h, b_h, w_s);
    k_knn<<<256, 256, knn_smem>>>();
    k_gather<<<NN / 4, 256>>>();
    k_lin<<<128, 256, lin_smem>>>(x, w_lin, b_lin);
    k_bnfin<<<1, 64>>>(gamma2, beta2, 0);
    k_mlp<<<128, 256>>>(w_p1, b_p1, w_p2, b_p2);
    k_bnfin<<<1, 64>>>(gamma3, beta3, 1);
    k_out<<<(NN * CC / 4) / 256, 256>>>(out);
}

// round 6
// speedup vs baseline: 7.1161x; 7.1161x over previous
#include <cuda_runtime.h>
#include <math.h>

#define NN 16384
#define CC 64
#define KK 40
#define TILE 512

// ---------------- scratch (device globals; no allocation allowed) ----------------
__device__ float  g_h[NN * CC];        // propagated features h = x@w_h + b_h
__device__ float4 g_s4[NN];            // learned coords (x,y,z,|s|^2)
__device__ int    g_knn[NN * KK];      // neighbor indices (unsorted top-40)
__device__ float  g_M[NN * 2 * CC];    // [mean | max] aggregation
__device__ float  g_t[NN * CC];        // xgn + x (input to BN2)
__device__ float  g_u[NN * CC];        // y + z (input to BN3)
__device__ float  g_sum2[CC], g_sumsq2[CC], g_sum3[CC], g_sumsq3[CC];
__device__ float  g_a2[CC], g_b2[CC], g_a3[CC], g_b3[CC];

// ---------------- K0: zero BN accumulators (must run every replay) ----------------
__global__ void k_zero() {
    int i = threadIdx.x;
    if (i < CC) { g_sum2[i] = 0.f; g_sumsq2[i] = 0.f; g_sum3[i] = 0.f; g_sumsq3[i] = 0.f; }
}

// ---------------- K1: h = x@w_h + b_h ; s = x@w_s ; store (s, |s|^2) ----------------
__global__ void __launch_bounds__(256) k_proj(
    const float* __restrict__ x, const float* __restrict__ w_h,
    const float* __restrict__ b_h, const float* __restrict__ w_s)
{
    __shared__ float wh[64 * 64];
    __shared__ float ws[64 * 4];
    __shared__ float bh[64];
    __shared__ float xr[4][64];
    int tid = threadIdx.x;
    for (int i = tid; i < 4096; i += 256) wh[i] = w_h[i];
    if (tid < 192) { int k = tid / 3, j = tid % 3; ws[k * 4 + j] = w_s[tid]; }
    if (tid < 64) bh[tid] = b_h[tid];
    __syncthreads();

    int c = tid & 63, sub = tid >> 6;
    int base = blockIdx.x * 128;
    for (int it = 0; it < 32; it++) {
        int n = base + it * 4 + sub;
        xr[sub][c] = x[n * 64 + c];
        __syncthreads();
        float acc = bh[c];
#pragma unroll
        for (int k = 0; k < 64; k++) acc = fmaf(xr[sub][k], wh[k * 64 + c], acc);
        g_h[n * 64 + c] = acc;
        if (c == 0) {
            float s0 = 0.f, s1 = 0.f, s2 = 0.f;
#pragma unroll
            for (int k = 0; k < 64; k++) {
                float xv = xr[sub][k];
                s0 = fmaf(xv, ws[k * 4 + 0], s0);
                s1 = fmaf(xv, ws[k * 4 + 1], s1);
                s2 = fmaf(xv, ws[k * 4 + 2], s2);
            }
            g_s4[n] = make_float4(s0, s1, s2, fmaf(s0, s0, fmaf(s1, s1, s2 * s2)));
        }
        __syncthreads();
    }
}

// ---------------- K2: brute-force exact kNN via 4-ary max-heap + buffered appends ----------------
// Column-major per-thread heap: hd/hi[slot][tid], stride 256 (bank-conflict-free).
// 4-ary heap over 40 slots: node i children 4i+1..4i+4; internal nodes 0..9; depth<=3.

extern __shared__ char dynraw[];

__device__ __forceinline__ void sift_from(float* hd, int* hi, int tid, int pos, float d, int j) {
#pragma unroll 3
    for (int lvl = 0; lvl < 3; lvl++) {
        int c1 = pos * 4 + 1;
        if (c1 >= KK) break;
        int mc = c1; float md = hd[c1 * 256 + tid];
        int e = KK - c1;
        if (e > 1) { float v = hd[(c1 + 1) * 256 + tid]; if (v > md) { md = v; mc = c1 + 1; } }
        if (e > 2) { float v = hd[(c1 + 2) * 256 + tid]; if (v > md) { md = v; mc = c1 + 2; } }
        if (e > 3) { float v = hd[(c1 + 3) * 256 + tid]; if (v > md) { md = v; mc = c1 + 3; } }
        if (md <= d) break;
        hd[pos * 256 + tid] = md; hi[pos * 256 + tid] = hi[mc * 256 + tid];
        pos = mc;
    }
    hd[pos * 256 + tid] = d; hi[pos * 256 + tid] = j;
}

__global__ void __launch_bounds__(256) k_knn()
{
    float*  hd   = (float*)dynraw;                        // [40][256] heap distances
    int*    hi   = (int*)(dynraw + 40 * 256 * 4);         // [40][256] heap indices
    float*  bd   = (float*)(dynraw + 80 * 256 * 4);       // [8][256]  buffer distances
    int*    bi   = (int*)(dynraw + 88 * 256 * 4);         // [8][256]  buffer indices
    float4* tile = (float4*)(dynraw + 96 * 256 * 4);      // [512]

    int tid = threadIdx.x;
    int q = tid >> 2, p = tid & 3;
    int Q = blockIdx.x * 64 + q;
    float4 qs = g_s4[Q];
    float qx = qs.x, qy = qs.y, qz = qs.z;

    // ---- prefill: first 40 candidates of this partition (global ids p+4k < 160) ----
#pragma unroll 8
    for (int k = 0; k < KK; k++) {
        int j = p + 4 * k;
        float4 cv = g_s4[j];
        float dx = qx - cv.x, dy = qy - cv.y, dz = qz - cv.z;
        float d = fmaf(dx, dx, fmaf(dy, dy, dz * dz));
        hd[k * 256 + tid] = d; hi[k * 256 + tid] = j;
    }
    // heapify (internal nodes 9..0)
#pragma unroll
    for (int i2 = 9; i2 >= 0; i2--) {
        float d = hd[i2 * 256 + tid]; int j = hi[i2 * 256 + tid];
        sift_from(hd, hi, tid, i2, d, j);
    }
    float worst = hd[tid];
    int bn = 0;

    for (int c0 = 0; c0 < NN; c0 += TILE) {
        __syncthreads();
        for (int j = tid; j < TILE; j += 256) tile[j] = g_s4[c0 + j];
        __syncthreads();
        int b0s = (c0 == 0) ? (p + 160) : p;   // skip prefilled candidates in tile 0
        for (int b0 = b0s; b0 < TILE; b0 += 16) {
            float4 cA = tile[b0];
            float4 cB = tile[b0 + 4];
            float4 cC = tile[b0 + 8];
            float4 cD = tile[b0 + 12];
            float dxA = qx - cA.x, dyA = qy - cA.y, dzA = qz - cA.z;
            float dxB = qx - cB.x, dyB = qy - cB.y, dzB = qz - cB.z;
            float dxC = qx - cC.x, dyC = qy - cC.y, dzC = qz - cC.z;
            float dxD = qx - cD.x, dyD = qy - cD.y, dzD = qz - cD.z;
            float dA = fmaf(dxA, dxA, fmaf(dyA, dyA, dzA * dzA));
            float dB = fmaf(dxB, dxB, fmaf(dyB, dyB, dzB * dzB));
            float dC = fmaf(dxC, dxC, fmaf(dyC, dyC, dzC * dzC));
            float dD = fmaf(dxD, dxD, fmaf(dyD, dyD, dzD * dzD));
            // cheap divergent appends (no heap work here)
            if (dA < worst) { bd[bn * 256 + tid] = dA; bi[bn * 256 + tid] = c0 + b0;      bn++; }
            if (dB < worst) { bd[bn * 256 + tid] = dB; bi[bn * 256 + tid] = c0 + b0 + 4;  bn++; }
            if (dC < worst) { bd[bn * 256 + tid] = dC; bi[bn * 256 + tid] = c0 + b0 + 8;  bn++; }
            if (dD < worst) { bd[bn * 256 + tid] = dD; bi[bn * 256 + tid] = c0 + b0 + 12; bn++; }
            // warp-uniform flush check (all lanes SIMT-concurrently drain their buffers)
            if (__any_sync(0xffffffffu, bn >= 5)) {
                for (int b = 0; b < bn; b++) {
                    float d = bd[b * 256 + tid];
                    if (d < hd[tid]) sift_from(hd, hi, tid, 0, d, bi[b * 256 + tid]);
                }
                bn = 0;
                worst = hd[tid];
            }
        }
    }
    // final flush
    for (int b = 0; b < bn; b++) {
        float d = bd[b * 256 + tid];
        if (d < hd[tid]) sift_from(hd, hi, tid, 0, d, bi[b * 256 + tid]);
    }
    __syncthreads();

    // merge the 4 partition heaps into partition 0's heap, write indices (unsorted OK)
    if (p == 0) {
        for (int o = 1; o < 4; o++) {
            for (int k = 0; k < KK; k++) {
                float d = hd[k * 256 + tid + o];
                if (d < hd[tid]) sift_from(hd, hi, tid, 0, d, hi[k * 256 + tid + o]);
            }
        }
        for (int r = 0; r < KK; r++) g_knn[Q * KK + r] = hi[r * 256 + tid];
    }
}

// ---------------- K3a: edge weights + mean/max message aggregation ----------------
__global__ void __launch_bounds__(256) k_gather()
{
    __shared__ int   jl[4][KK];
    __shared__ float wl[4][KK];
    int tid = threadIdx.x;
    int g = tid >> 6, c = tid & 63;
    int i = blockIdx.x * 4 + g;
    if (c < KK) {
        int j = g_knn[i * KK + c];
        float4 sj = g_s4[j];
        float4 si_ = g_s4[i];
        float dx = si_.x - sj.x, dy = si_.y - sj.y, dz = si_.z - sj.z;
        float d2 = dx * dx + dy * dy + dz * dz;
        jl[g][c] = j;
        wl[g][c] = expf(-(d2 + 1e-6f));
    }
    __syncthreads();
    float sum = 0.f, mx = -3.4e38f;
#pragma unroll
    for (int k = 0; k < KK; k++) {
        float m = wl[g][k] * g_h[jl[g][k] * 64 + c];
        sum += m;
        mx = fmaxf(mx, m);
    }
    g_M[i * 128 + c] = sum * (1.0f / KK);
    g_M[i * 128 + 64 + c] = mx;
}

// ---------------- K3b: t = [mean|max|x] @ w_lin + b_lin + x ; BN2 partial sums ----------------
__global__ void __launch_bounds__(256) k_lin(
    const float* __restrict__ x, const float* __restrict__ w_lin,
    const float* __restrict__ b_lin)
{
    float* wl = (float*)dynraw;              // [192*64]
    float* ar = (float*)dynraw + 192 * 64;   // [4][192]
    __shared__ float bl[64];
    __shared__ float red[2][4][64];
    int tid = threadIdx.x;
    for (int i = tid; i < 192 * 64; i += 256) wl[i] = w_lin[i];
    if (tid < 64) bl[tid] = b_lin[tid];
    __syncthreads();

    int c = tid & 63, sub = tid >> 6;
    int base = blockIdx.x * 128;
    float psum = 0.f, psq = 0.f;
    for (int it = 0; it < 32; it++) {
        int n = base + it * 4 + sub;
        ar[sub * 192 + c]       = g_M[n * 128 + c];
        ar[sub * 192 + 64 + c]  = g_M[n * 128 + 64 + c];
        ar[sub * 192 + 128 + c] = x[n * 64 + c];
        __syncthreads();
        float acc = bl[c] + ar[sub * 192 + 128 + c];   // + residual x
#pragma unroll
        for (int f = 0; f < 192; f++) acc = fmaf(ar[sub * 192 + f], wl[f * 64 + c], acc);
        g_t[n * 64 + c] = acc;
        psum += acc;
        psq = fmaf(acc, acc, psq);
        __syncthreads();
    }
    red[0][sub][c] = psum;
    red[1][sub][c] = psq;
    __syncthreads();
    if (sub == 0) {
        float s  = red[0][0][c] + red[0][1][c] + red[0][2][c] + red[0][3][c];
        float s2 = red[1][0][c] + red[1][1][c] + red[1][2][c] + red[1][3][c];
        atomicAdd(&g_sum2[c], s);
        atomicAdd(&g_sumsq2[c], s2);
    }
}

// ---------------- K4/K6: finalize BN affine params ----------------
__global__ void k_bnfin(const float* __restrict__ gamma, const float* __restrict__ beta, int which)
{
    int c = threadIdx.x;
    if (c < CC) {
        float s  = which ? g_sum3[c]   : g_sum2[c];
        float s2 = which ? g_sumsq3[c] : g_sumsq2[c];
        float mu  = s * (1.0f / NN);
        float var = s2 * (1.0f / NN) - mu * mu;
        float ai = gamma[c] * rsqrtf(var + 1e-5f);
        float bi = beta[c] - ai * mu;
        if (which) { g_a3[c] = ai; g_b3[c] = bi; }
        else       { g_a2[c] = ai; g_b2[c] = bi; }
    }
}

// ---------------- K5: y = BN2(t); z = elu(y@w_p1+b_p1)@w_p2+b_p2; u = y+z ; BN3 sums ----------------
__global__ void __launch_bounds__(256) k_mlp(
    const float* __restrict__ w_p1, const float* __restrict__ b_p1,
    const float* __restrict__ w_p2, const float* __restrict__ b_p2)
{
    __shared__ float w1[4096], w2[4096], b1s[64], b2s[64], aas[64], bbs[64];
    __shared__ float yr[4][64], vr[4][64];
    __shared__ float red[2][4][64];
    int tid = threadIdx.x;
    for (int i = tid; i < 4096; i += 256) { w1[i] = w_p1[i]; w2[i] = w_p2[i]; }
    if (tid < 64) { b1s[tid] = b_p1[tid]; b2s[tid] = b_p2[tid]; aas[tid] = g_a2[tid]; bbs[tid] = g_b2[tid]; }
    __syncthreads();

    int c = tid & 63, sub = tid >> 6;
    int base = blockIdx.x * 128;
    float psum = 0.f, psq = 0.f;
    for (int it = 0; it < 32; it++) {
        int n = base + it * 4 + sub;
        float yv = fmaf(aas[c], g_t[n * 64 + c], bbs[c]);
        yr[sub][c] = yv;
        __syncthreads();
        float a1 = b1s[c];
#pragma unroll
        for (int k = 0; k < 64; k++) a1 = fmaf(yr[sub][k], w1[k * 64 + c], a1);
        float v = a1 > 0.f ? a1 : expm1f(a1);
        vr[sub][c] = v;
        __syncthreads();
        float a2v = b2s[c];
#pragma unroll
        for (int k = 0; k < 64; k++) a2v = fmaf(vr[sub][k], w2[k * 64 + c], a2v);
        float u = yv + a2v;
        g_u[n * 64 + c] = u;
        psum += u;
        psq = fmaf(u, u, psq);
        __syncthreads();
    }
    red[0][sub][c] = psum;
    red[1][sub][c] = psq;
    __syncthreads();
    if (sub == 0) {
        float s  = red[0][0][c] + red[0][1][c] + red[0][2][c] + red[0][3][c];
        float s2 = red[1][0][c] + red[1][1][c] + red[1][2][c] + red[1][3][c];
        atomicAdd(&g_sum3[c], s);
        atomicAdd(&g_sumsq3[c], s2);
    }
}

// ---------------- K7: out = BN3(u) ----------------
__global__ void __launch_bounds__(256) k_out(float* __restrict__ out)
{
    int idx = blockIdx.x * 256 + threadIdx.x;   // over N*C/4 float4
    const float4* u4 = (const float4*)g_u;
    float4 v = u4[idx];
    int c = (idx * 4) & 63;
    float4 r;
    r.x = fmaf(g_a3[c + 0], v.x, g_b3[c + 0]);
    r.y = fmaf(g_a3[c + 1], v.y, g_b3[c + 1]);
    r.z = fmaf(g_a3[c + 2], v.z, g_b3[c + 2]);
    r.w = fmaf(g_a3[c + 3], v.w, g_b3[c + 3]);
    ((float4*)out)[idx] = r;
}

// ---------------- launch ----------------
extern "C" void kernel_launch(void* const* d_in, const int* in_sizes, int n_in,
                              void* d_out, int out_size)
{
    const float* x     = (const float*)d_in[0];
    const float* w_s   = (const float*)d_in[1];
    const float* w_h   = (const float*)d_in[2];
    const float* b_h   = (const float*)d_in[3];
    const float* w_lin = (const float*)d_in[4];
    const float* b_lin = (const float*)d_in[5];
    const float* w_p1  = (const float*)d_in[6];
    const float* b_p1  = (const float*)d_in[7];
    const float* w_p2  = (const float*)d_in[8];
    const float* b_p2  = (const float*)d_in[9];
    const float* gamma2 = (const float*)d_in[10];
    const float* beta2  = (const float*)d_in[11];
    const float* gamma3 = (const float*)d_in[12];
    const float* beta3  = (const float*)d_in[13];
    float* out = (float*)d_out;

    const int knn_smem = 96 * 256 * 4 + TILE * 16;       // 106496 B (heaps+buffers+tile)
    const int lin_smem = (192 * 64 + 4 * 192) * 4;       // 52224 B
    cudaFuncSetAttribute(k_knn, cudaFuncAttributeMaxDynamicSharedMemorySize, knn_smem);
    cudaFuncSetAttribute(k_lin, cudaFuncAttributeMaxDynamicSharedMemorySize, lin_smem);

    k_zero<<<1, 64>>>();
    k_proj<<<128, 256>>>(x, w_h, b_h, w_s);
    k_knn<<<256, 256, knn_smem>>>();
    k_gather<<<NN / 4, 256>>>();
    k_lin<<<128, 256, lin_smem>>>(x, w_lin, b_lin);
    k_bnfin<<<1, 64>>>(gamma2, beta2, 0);
    k_mlp<<<128, 256>>>(w_p1, b_p1, w_p2, b_p2);
    k_bnfin<<<1, 64>>>(gamma3, beta3, 1);
    k_out<<<(NN * CC / 4) / 256, 256>>>(out);
}

// round 7
// speedup vs baseline: 7.2902x; 1.0245x over previous
#include <cuda_runtime.h>
#include <math.h>

#define NN 16384
#define CC 64
#define KK 40
#define TILE 512
#define BUFD 12

// ---------------- scratch (device globals; no allocation allowed) ----------------
__device__ float  g_h[NN * CC];        // propagated features h = x@w_h + b_h
__device__ float4 g_s4[NN];            // learned coords (x,y,z,|s|^2)
__device__ int    g_knn[NN * KK];      // neighbor indices (unsorted top-40)
__device__ float  g_M[NN * 2 * CC];    // [mean | max] aggregation
__device__ float  g_t[NN * CC];        // xgn + x (input to BN2)
__device__ float  g_u[NN * CC];        // y + z (input to BN3)
__device__ float  g_sum2[CC], g_sumsq2[CC], g_sum3[CC], g_sumsq3[CC];
__device__ float  g_a2[CC], g_b2[CC], g_a3[CC], g_b3[CC];

// ---------------- K0: zero BN accumulators (must run every replay) ----------------
__global__ void k_zero() {
    int i = threadIdx.x;
    if (i < CC) { g_sum2[i] = 0.f; g_sumsq2[i] = 0.f; g_sum3[i] = 0.f; g_sumsq3[i] = 0.f; }
}

// ---------------- K1: h = x@w_h + b_h ; s = x@w_s ; store (s, |s|^2) ----------------
__global__ void __launch_bounds__(256) k_proj(
    const float* __restrict__ x, const float* __restrict__ w_h,
    const float* __restrict__ b_h, const float* __restrict__ w_s)
{
    __shared__ float wh[64 * 64];
    __shared__ float ws[64 * 4];
    __shared__ float bh[64];
    __shared__ float xr[4][64];
    int tid = threadIdx.x;
    for (int i = tid; i < 4096; i += 256) wh[i] = w_h[i];
    if (tid < 192) { int k = tid / 3, j = tid % 3; ws[k * 4 + j] = w_s[tid]; }
    if (tid < 64) bh[tid] = b_h[tid];
    __syncthreads();

    int c = tid & 63, sub = tid >> 6;
    int base = blockIdx.x * 128;
    for (int it = 0; it < 32; it++) {
        int n = base + it * 4 + sub;
        xr[sub][c] = x[n * 64 + c];
        __syncthreads();
        float acc = bh[c];
#pragma unroll
        for (int k = 0; k < 64; k++) acc = fmaf(xr[sub][k], wh[k * 64 + c], acc);
        g_h[n * 64 + c] = acc;
        if (c == 0) {
            float s0 = 0.f, s1 = 0.f, s2 = 0.f;
#pragma unroll
            for (int k = 0; k < 64; k++) {
                float xv = xr[sub][k];
                s0 = fmaf(xv, ws[k * 4 + 0], s0);
                s1 = fmaf(xv, ws[k * 4 + 1], s1);
                s2 = fmaf(xv, ws[k * 4 + 2], s2);
            }
            g_s4[n] = make_float4(s0, s1, s2, fmaf(s0, s0, fmaf(s1, s1, s2 * s2)));
        }
        __syncthreads();
    }
}

// ---------------- K2: brute-force exact kNN via 4-ary max-heap + buffered appends ----------------
// Scoring: t = |c|^2 - 2 q.c  (monotone in d^2 for fixed q; 3 FFMA/candidate).
// Column-major per-thread heap: hd/hi[slot][tid], stride 256 (bank-conflict-free).
// 4-ary heap over 40 slots: node i children 4i+1..4i+4; internal nodes 0..9; depth<=3.

extern __shared__ char dynraw[];

__device__ __forceinline__ void sift_from(float* hd, int* hi, int tid, int pos, float d, int j) {
#pragma unroll 3
    for (int lvl = 0; lvl < 3; lvl++) {
        int c1 = pos * 4 + 1;
        if (c1 >= KK) break;
        int mc = c1; float md = hd[c1 * 256 + tid];
        int e = KK - c1;
        if (e > 1) { float v = hd[(c1 + 1) * 256 + tid]; if (v > md) { md = v; mc = c1 + 1; } }
        if (e > 2) { float v = hd[(c1 + 2) * 256 + tid]; if (v > md) { md = v; mc = c1 + 2; } }
        if (e > 3) { float v = hd[(c1 + 3) * 256 + tid]; if (v > md) { md = v; mc = c1 + 3; } }
        if (md <= d) break;
        hd[pos * 256 + tid] = md; hi[pos * 256 + tid] = hi[mc * 256 + tid];
        pos = mc;
    }
    hd[pos * 256 + tid] = d; hi[pos * 256 + tid] = j;
}

__global__ void __launch_bounds__(256) k_knn()
{
    float*  hd   = (float*)dynraw;                               // [40][256] heap scores
    int*    hi   = (int*)(dynraw + 40 * 256 * 4);                // [40][256] heap indices
    float*  bd   = (float*)(dynraw + 80 * 256 * 4);              // [BUFD][256] buffer scores
    int*    bi   = (int*)(dynraw + (80 + BUFD) * 256 * 4);       // [BUFD][256] buffer indices
    float4* tile = (float4*)(dynraw + (80 + 2 * BUFD) * 256 * 4);// [TILE]

    int tid = threadIdx.x;
    int q = tid >> 2, p = tid & 3;
    int Q = blockIdx.x * 64 + q;
    float4 qs = g_s4[Q];
    float m2x = -2.0f * qs.x, m2y = -2.0f * qs.y, m2z = -2.0f * qs.z;

    // ---- prefill: first 40 candidates of this partition (global ids p+4k, k<40) ----
#pragma unroll 8
    for (int k = 0; k < KK; k++) {
        int j = p + 4 * k;
        float4 cv = g_s4[j];
        float t = fmaf(cv.x, m2x, fmaf(cv.y, m2y, fmaf(cv.z, m2z, cv.w)));
        hd[k * 256 + tid] = t; hi[k * 256 + tid] = j;
    }
    // heapify (internal nodes 9..0)
#pragma unroll
    for (int i2 = 9; i2 >= 0; i2--) {
        float d = hd[i2 * 256 + tid]; int j = hi[i2 * 256 + tid];
        sift_from(hd, hi, tid, i2, d, j);
    }
    float worst = hd[tid];
    int bn = 0;

    for (int c0 = 0; c0 < NN; c0 += TILE) {
        __syncthreads();
        for (int j = tid; j < TILE; j += 256) tile[j] = g_s4[c0 + j];
        __syncthreads();
        // tile 0: candidates p+4m with m<40 are prefilled; they occupy groups 0..4 exactly
        int g0 = (c0 == 0) ? 5 : 0;
        for (int g8 = g0; g8 < TILE / 32; g8++) {
            int base = g8 * 32 + p;
            float ts[8];
#pragma unroll
            for (int j = 0; j < 8; j++) {
                float4 cv = tile[base + 4 * j];
                ts[j] = fmaf(cv.x, m2x, fmaf(cv.y, m2y, fmaf(cv.z, m2z, cv.w)));
            }
#pragma unroll
            for (int j = 0; j < 8; j++) {
                if (ts[j] < worst) {
                    bd[bn * 256 + tid] = ts[j];
                    bi[bn * 256 + tid] = c0 + base + 4 * j;
                    bn++;
                }
            }
            // warp-uniform flush (max 8 appends/group; post-flush bn<=4, so bn<=12=BUFD)
            if (__any_sync(0xffffffffu, bn >= 5)) {
                for (int b = 0; b < bn; b++) {
                    float d = bd[b * 256 + tid];
                    if (d < hd[tid]) sift_from(hd, hi, tid, 0, d, bi[b * 256 + tid]);
                }
                bn = 0;
                worst = hd[tid];
            }
        }
    }
    // final flush
    for (int b = 0; b < bn; b++) {
        float d = bd[b * 256 + tid];
        if (d < hd[tid]) sift_from(hd, hi, tid, 0, d, bi[b * 256 + tid]);
    }
    __syncthreads();

    // merge the 4 partition heaps into partition 0's heap, write indices (unsorted OK)
    if (p == 0) {
        for (int o = 1; o < 4; o++) {
            for (int k = 0; k < KK; k++) {
                float d = hd[k * 256 + tid + o];
                if (d < hd[tid]) sift_from(hd, hi, tid, 0, d, hi[k * 256 + tid + o]);
            }
        }
        for (int r = 0; r < KK; r++) g_knn[Q * KK + r] = hi[r * 256 + tid];
    }
}

// ---------------- K3a: edge weights + mean/max message aggregation ----------------
__global__ void __launch_bounds__(256) k_gather()
{
    __shared__ int   jl[4][KK];
    __shared__ float wl[4][KK];
    int tid = threadIdx.x;
    int g = tid >> 6, c = tid & 63;
    int i = blockIdx.x * 4 + g;
    if (c < KK) {
        int j = g_knn[i * KK + c];
        float4 sj = g_s4[j];
        float4 si_ = g_s4[i];
        float dx = si_.x - sj.x, dy = si_.y - sj.y, dz = si_.z - sj.z;
        float d2 = dx * dx + dy * dy + dz * dz;
        jl[g][c] = j;
        wl[g][c] = expf(-(d2 + 1e-6f));
    }
    __syncthreads();
    float sum = 0.f, mx = -3.4e38f;
#pragma unroll
    for (int k = 0; k < KK; k++) {
        float m = wl[g][k] * g_h[jl[g][k] * 64 + c];
        sum += m;
        mx = fmaxf(mx, m);
    }
    g_M[i * 128 + c] = sum * (1.0f / KK);
    g_M[i * 128 + 64 + c] = mx;
}

// ---------------- K3b: t = [mean|max|x] @ w_lin + b_lin + x ; BN2 partial sums ----------------
__global__ void __launch_bounds__(256) k_lin(
    const float* __restrict__ x, const float* __restrict__ w_lin,
    const float* __restrict__ b_lin)
{
    float* wl = (float*)dynraw;              // [192*64]
    float* ar = (float*)dynraw + 192 * 64;   // [4][192]
    __shared__ float bl[64];
    __shared__ float red[2][4][64];
    int tid = threadIdx.x;
    for (int i = tid; i < 192 * 64; i += 256) wl[i] = w_lin[i];
    if (tid < 64) bl[tid] = b_lin[tid];
    __syncthreads();

    int c = tid & 63, sub = tid >> 6;
    int base = blockIdx.x * 128;
    float psum = 0.f, psq = 0.f;
    for (int it = 0; it < 32; it++) {
        int n = base + it * 4 + sub;
        ar[sub * 192 + c]       = g_M[n * 128 + c];
        ar[sub * 192 + 64 + c]  = g_M[n * 128 + 64 + c];
        ar[sub * 192 + 128 + c] = x[n * 64 + c];
        __syncthreads();
        float acc = bl[c] + ar[sub * 192 + 128 + c];   // + residual x
#pragma unroll
        for (int f = 0; f < 192; f++) acc = fmaf(ar[sub * 192 + f], wl[f * 64 + c], acc);
        g_t[n * 64 + c] = acc;
        psum += acc;
        psq = fmaf(acc, acc, psq);
        __syncthreads();
    }
    red[0][sub][c] = psum;
    red[1][sub][c] = psq;
    __syncthreads();
    if (sub == 0) {
        float s  = red[0][0][c] + red[0][1][c] + red[0][2][c] + red[0][3][c];
        float s2 = red[1][0][c] + red[1][1][c] + red[1][2][c] + red[1][3][c];
        atomicAdd(&g_sum2[c], s);
        atomicAdd(&g_sumsq2[c], s2);
    }
}

// ---------------- K4/K6: finalize BN affine params ----------------
__global__ void k_bnfin(const float* __restrict__ gamma, const float* __restrict__ beta, int which)
{
    int c = threadIdx.x;
    if (c < CC) {
        float s  = which ? g_sum3[c]   : g_sum2[c];
        float s2 = which ? g_sumsq3[c] : g_sumsq2[c];
        float mu  = s * (1.0f / NN);
        float var = s2 * (1.0f / NN) - mu * mu;
        float ai = gamma[c] * rsqrtf(var + 1e-5f);
        float bi = beta[c] - ai * mu;
        if (which) { g_a3[c] = ai; g_b3[c] = bi; }
        else       { g_a2[c] = ai; g_b2[c] = bi; }
    }
}

// ---------------- K5: y = BN2(t); z = elu(y@w_p1+b_p1)@w_p2+b_p2; u = y+z ; BN3 sums ----------------
__global__ void __launch_bounds__(256) k_mlp(
    const float* __restrict__ w_p1, const float* __restrict__ b_p1,
    const float* __restrict__ w_p2, const float* __restrict__ b_p2)
{
    __shared__ float w1[4096], w2[4096], b1s[64], b2s[64], aas[64], bbs[64];
    __shared__ float yr[4][64], vr[4][64];
    __shared__ float red[2][4][64];
    int tid = threadIdx.x;
    for (int i = tid; i < 4096; i += 256) { w1[i] = w_p1[i]; w2[i] = w_p2[i]; }
    if (tid < 64) { b1s[tid] = b_p1[tid]; b2s[tid] = b_p2[tid]; aas[tid] = g_a2[tid]; bbs[tid] = g_b2[tid]; }
    __syncthreads();

    int c = tid & 63, sub = tid >> 6;
    int base = blockIdx.x * 128;
    float psum = 0.f, psq = 0.f;
    for (int it = 0; it < 32; it++) {
        int n = base + it * 4 + sub;
        float yv = fmaf(aas[c], g_t[n * 64 + c], bbs[c]);
        yr[sub][c] = yv;
        __syncthreads();
        float a1 = b1s[c];
#pragma unroll
        for (int k = 0; k < 64; k++) a1 = fmaf(yr[sub][k], w1[k * 64 + c], a1);
        float v = a1 > 0.f ? a1 : expm1f(a1);
        vr[sub][c] = v;
        __syncthreads();
        float a2v = b2s[c];
#pragma unroll
        for (int k = 0; k < 64; k++) a2v = fmaf(vr[sub][k], w2[k * 64 + c], a2v);
        float u = yv + a2v;
        g_u[n * 64 + c] = u;
        psum += u;
        psq = fmaf(u, u, psq);
        __syncthreads();
    }
    red[0][sub][c] = psum;
    red[1][sub][c] = psq;
    __syncthreads();
    if (sub == 0) {
        float s  = red[0][0][c] + red[0][1][c] + red[0][2][c] + red[0][3][c];
        float s2 = red[1][0][c] + red[1][1][c] + red[1][2][c] + red[1][3][c];
        atomicAdd(&g_sum3[c], s);
        atomicAdd(&g_sumsq3[c], s2);
    }
}

// ---------------- K7: out = BN3(u) ----------------
__global__ void __launch_bounds__(256) k_out(float* __restrict__ out)
{
    int idx = blockIdx.x * 256 + threadIdx.x;   // over N*C/4 float4
    const float4* u4 = (const float4*)g_u;
    float4 v = u4[idx];
    int c = (idx * 4) & 63;
    float4 r;
    r.x = fmaf(g_a3[c + 0], v.x, g_b3[c + 0]);
    r.y = fmaf(g_a3[c + 1], v.y, g_b3[c + 1]);
    r.z = fmaf(g_a3[c + 2], v.z, g_b3[c + 2]);
    r.w = fmaf(g_a3[c + 3], v.w, g_b3[c + 3]);
    ((float4*)out)[idx] = r;
}

// ---------------- launch ----------------
extern "C" void kernel_launch(void* const* d_in, const int* in_sizes, int n_in,
                              void* d_out, int out_size)
{
    const float* x     = (const float*)d_in[0];
    const float* w_s   = (const float*)d_in[1];
    const float* w_h   = (const float*)d_in[2];
    const float* b_h   = (const float*)d_in[3];
    const float* w_lin = (const float*)d_in[4];
    const float* b_lin = (const float*)d_in[5];
    const float* w_p1  = (const float*)d_in[6];
    const float* b_p1  = (const float*)d_in[7];
    const float* w_p2  = (const float*)d_in[8];
    const float* b_p2  = (const float*)d_in[9];
    const float* gamma2 = (const float*)d_in[10];
    const float* beta2  = (const float*)d_in[11];
    const float* gamma3 = (const float*)d_in[12];
    const float* beta3  = (const float*)d_in[13];
    float* out = (float*)d_out;

    const int knn_smem = (80 + 2 * BUFD) * 256 * 4 + TILE * 16;  // 114688 B
    const int lin_smem = (192 * 64 + 4 * 192) * 4;               // 52224 B
    cudaFuncSetAttribute(k_knn, cudaFuncAttributeMaxDynamicSharedMemorySize, knn_smem);
    cudaFuncSetAttribute(k_lin, cudaFuncAttributeMaxDynamicSharedMemorySize, lin_smem);

    k_zero<<<1, 64>>>();
    k_proj<<<128, 256>>>(x, w_h, b_h, w_s);
    k_knn<<<256, 256, knn_smem>>>();
    k_gather<<<NN / 4, 256>>>();
    k_lin<<<128, 256, lin_smem>>>(x, w_lin, b_lin);
    k_bnfin<<<1, 64>>>(gamma2, beta2, 0);
    k_mlp<<<128, 256>>>(w_p1, b_p1, w_p2, b_p2);
    k_bnfin<<<1, 64>>>(gamma3, beta3, 1);
    k_out<<<(NN * CC / 4) / 256, 256>>>(out);
}